// round 6
// baseline (speedup 1.0000x reference)
#include <cuda_runtime.h>
#include <math.h>
#include <stdint.h>

#define F   256
#define NG  1024

// ---------------- scratch ----------------
__device__ float g_acc[NG * F];   // unnormalized weighted feature sums (atomic)
__device__ float g_s[NG];         // unnormalized softmax denominators (atomic)
__device__ float g_x[NG * F];     // elu(proj(wf))

// ---------------- f32x2 packed-math helpers ----------------
__device__ __forceinline__ uint64_t pack2(float x, float y) {
    uint64_t r; asm("mov.b64 %0, {%1, %2};" : "=l"(r) : "f"(x), "f"(y)); return r;
}
__device__ __forceinline__ uint64_t bcast2(float x) {
    uint64_t r; asm("mov.b64 %0, {%1, %1};" : "=l"(r) : "f"(x)); return r;
}
__device__ __forceinline__ void ffma2(uint64_t& d, uint64_t a, uint64_t b) {
    asm("fma.rn.f32x2 %0, %1, %2, %0;" : "+l"(d) : "l"(a), "l"(b));
}
__device__ __forceinline__ float2 unpack2(uint64_t v) {
    float2 f; asm("mov.b64 {%0, %1}, %2;" : "=f"(f.x), "=f"(f.y) : "l"(v)); return f;
}
__device__ __forceinline__ float fast_tanh(float x) {
    float r; asm("tanh.approx.f32 %0, %1;" : "=f"(r) : "f"(x)); return r;
}
__device__ __forceinline__ float4 ldcs4(const float4* p) {
    float4 v;
    asm("ld.global.cs.v4.f32 {%0,%1,%2,%3}, [%4];"
        : "=f"(v.x), "=f"(v.y), "=f"(v.z), "=f"(v.w) : "l"(p));
    return v;
}

// ---------------- zero kernel: clear atomic accumulators ----------------
__global__ void __launch_bounds__(256) zero_kernel() {
    int i = blockIdx.x * 256 + threadIdx.x;          // grid 256 -> 65536 float4
    reinterpret_cast<float4*>(g_acc)[i] = make_float4(0.f, 0.f, 0.f, 0.f);
    if (blockIdx.x == 0)
        reinterpret_cast<float4*>(g_s)[threadIdx.x] = make_float4(0.f, 0.f, 0.f, 0.f);
}

// ---------------- pool: chunked, contiguous, atomic flush ----------------
// Unnormalized softmax accumulation (scale cancels in acc/S; z bounded for
// unit-normal inputs). Each warp owns 32 contiguous nodes; 4 nodes/iter with
// 8 front-batched streaming LDG.128. On (rare) segment change, flush register
// accumulators to global via atomicAdd.
__global__ void __launch_bounds__(256) pool_kernel(
    const float* __restrict__ nf, const float* __restrict__ gf,
    const float* __restrict__ lw, const float* __restrict__ lb,
    const int* __restrict__ seg, int n_nodes)
{
    const int warp = threadIdx.x >> 5;
    const int lane = threadIdx.x & 31;
    const int n0   = blockIdx.x * 256 + warp * 32;
    if (n0 >= n_nodes) return;
    const int cnt = min(32, n_nodes - n0);

    // per-lane chunks of logit_w: lw1 = graph half, lw2 = node half
    float lw1[8], lw2[8];
    {
        const float4* p1 = reinterpret_cast<const float4*>(lw) + lane * 2;
        float4 a = __ldg(p1), b = __ldg(p1 + 1);
        lw1[0]=a.x; lw1[1]=a.y; lw1[2]=a.z; lw1[3]=a.w;
        lw1[4]=b.x; lw1[5]=b.y; lw1[6]=b.z; lw1[7]=b.w;
        const float4* p2 = reinterpret_cast<const float4*>(lw + F) + lane * 2;
        float4 c2 = __ldg(p2), d2 = __ldg(p2 + 1);
        lw2[0]=c2.x; lw2[1]=c2.y; lw2[2]=c2.z; lw2[3]=c2.w;
        lw2[4]=d2.x; lw2[5]=d2.y; lw2[6]=d2.z; lw2[7]=d2.w;
    }
    const float lb0 = __ldg(lb);

    // segment id of each of this warp's nodes, one per lane
    int sid = (lane < cnt) ? __ldg(seg + n0 + lane) : -1;

    // c_g = relu(g_feats[g]) . lw1 + lb  (uniform across warp after butterfly)
    auto calc_c = [&](int g) -> float {
        const float4* gp = reinterpret_cast<const float4*>(gf + (size_t)g * F) + lane * 2;
        float4 x0 = __ldg(gp), x1 = __ldg(gp + 1);
        float v = fmaxf(x0.x, 0.f) * lw1[0];
        v = fmaf(fmaxf(x0.y, 0.f), lw1[1], v);
        v = fmaf(fmaxf(x0.z, 0.f), lw1[2], v);
        v = fmaf(fmaxf(x0.w, 0.f), lw1[3], v);
        v = fmaf(fmaxf(x1.x, 0.f), lw1[4], v);
        v = fmaf(fmaxf(x1.y, 0.f), lw1[5], v);
        v = fmaf(fmaxf(x1.z, 0.f), lw1[6], v);
        v = fmaf(fmaxf(x1.w, 0.f), lw1[7], v);
        #pragma unroll
        for (int o = 16; o; o >>= 1) v += __shfl_xor_sync(0xffffffffu, v, o);
        return v + lb0;
    };

    int   cur = __shfl_sync(0xffffffffu, sid, 0);
    float c   = calc_c(cur);
    float s   = 0.f;
    float acc[8] = {0.f, 0.f, 0.f, 0.f, 0.f, 0.f, 0.f, 0.f};

    auto flush = [&]() {
        float* bp = g_acc + (size_t)cur * F + lane * 8;
        #pragma unroll
        for (int k = 0; k < 8; ++k) { atomicAdd(bp + k, acc[k]); acc[k] = 0.f; }
        if (lane == 0) atomicAdd(g_s + cur, s);
        s = 0.f;
    };

    auto accum1 = [&](float e, const float4& f0, const float4& f1) {
        s += e;
        acc[0] = fmaf(e, f0.x, acc[0]);
        acc[1] = fmaf(e, f0.y, acc[1]);
        acc[2] = fmaf(e, f0.z, acc[2]);
        acc[3] = fmaf(e, f0.w, acc[3]);
        acc[4] = fmaf(e, f1.x, acc[4]);
        acc[5] = fmaf(e, f1.y, acc[5]);
        acc[6] = fmaf(e, f1.z, acc[6]);
        acc[7] = fmaf(e, f1.w, acc[7]);
    };

    int i = 0;
    for (; i + 4 <= cnt; i += 4) {
        const float4* p0 = reinterpret_cast<const float4*>(nf + (size_t)(n0 + i) * F) + lane * 2;
        float4 a0 = ldcs4(p0),       a1 = ldcs4(p0 + 1);
        float4 b0 = ldcs4(p0 + 64),  b1 = ldcs4(p0 + 65);
        float4 c0 = ldcs4(p0 + 128), c1 = ldcs4(p0 + 129);
        float4 d0 = ldcs4(p0 + 192), d1 = ldcs4(p0 + 193);

        float q1 = a0.x * lw2[0], q2 = b0.x * lw2[0];
        float q3 = c0.x * lw2[0], q4 = d0.x * lw2[0];
        q1 = fmaf(a0.y, lw2[1], q1); q2 = fmaf(b0.y, lw2[1], q2);
        q3 = fmaf(c0.y, lw2[1], q3); q4 = fmaf(d0.y, lw2[1], q4);
        q1 = fmaf(a0.z, lw2[2], q1); q2 = fmaf(b0.z, lw2[2], q2);
        q3 = fmaf(c0.z, lw2[2], q3); q4 = fmaf(d0.z, lw2[2], q4);
        q1 = fmaf(a0.w, lw2[3], q1); q2 = fmaf(b0.w, lw2[3], q2);
        q3 = fmaf(c0.w, lw2[3], q3); q4 = fmaf(d0.w, lw2[3], q4);
        q1 = fmaf(a1.x, lw2[4], q1); q2 = fmaf(b1.x, lw2[4], q2);
        q3 = fmaf(c1.x, lw2[4], q3); q4 = fmaf(d1.x, lw2[4], q4);
        q1 = fmaf(a1.y, lw2[5], q1); q2 = fmaf(b1.y, lw2[5], q2);
        q3 = fmaf(c1.y, lw2[5], q3); q4 = fmaf(d1.y, lw2[5], q4);
        q1 = fmaf(a1.z, lw2[6], q1); q2 = fmaf(b1.z, lw2[6], q2);
        q3 = fmaf(c1.z, lw2[6], q3); q4 = fmaf(d1.z, lw2[6], q4);
        q1 = fmaf(a1.w, lw2[7], q1); q2 = fmaf(b1.w, lw2[7], q2);
        q3 = fmaf(c1.w, lw2[7], q3); q4 = fmaf(d1.w, lw2[7], q4);
        #pragma unroll
        for (int o = 16; o; o >>= 1) {
            q1 += __shfl_xor_sync(0xffffffffu, q1, o);
            q2 += __shfl_xor_sync(0xffffffffu, q2, o);
            q3 += __shfl_xor_sync(0xffffffffu, q3, o);
            q4 += __shfl_xor_sync(0xffffffffu, q4, o);
        }

        int s0 = __shfl_sync(0xffffffffu, sid, i);
        int s3 = __shfl_sync(0xffffffffu, sid, i + 3);
        if (s0 == cur && s3 == cur) {
            // fast path: all 4 nodes in current graph
            float t1 = c + q1, t2 = c + q2, t3 = c + q3, t4 = c + q4;
            float z1 = t1 > 0.f ? t1 : 0.01f * t1;
            float z2 = t2 > 0.f ? t2 : 0.01f * t2;
            float z3 = t3 > 0.f ? t3 : 0.01f * t3;
            float z4 = t4 > 0.f ? t4 : 0.01f * t4;
            float e1 = __expf(z1), e2 = __expf(z2);
            float e3 = __expf(z3), e4 = __expf(z4);
            s += (e1 + e2) + (e3 + e4);
            acc[0] = fmaf(e1, a0.x, fmaf(e2, b0.x, fmaf(e3, c0.x, fmaf(e4, d0.x, acc[0]))));
            acc[1] = fmaf(e1, a0.y, fmaf(e2, b0.y, fmaf(e3, c0.y, fmaf(e4, d0.y, acc[1]))));
            acc[2] = fmaf(e1, a0.z, fmaf(e2, b0.z, fmaf(e3, c0.z, fmaf(e4, d0.z, acc[2]))));
            acc[3] = fmaf(e1, a0.w, fmaf(e2, b0.w, fmaf(e3, c0.w, fmaf(e4, d0.w, acc[3]))));
            acc[4] = fmaf(e1, a1.x, fmaf(e2, b1.x, fmaf(e3, c1.x, fmaf(e4, d1.x, acc[4]))));
            acc[5] = fmaf(e1, a1.y, fmaf(e2, b1.y, fmaf(e3, c1.y, fmaf(e4, d1.y, acc[5]))));
            acc[6] = fmaf(e1, a1.z, fmaf(e2, b1.z, fmaf(e3, c1.z, fmaf(e4, d1.z, acc[6]))));
            acc[7] = fmaf(e1, a1.w, fmaf(e2, b1.w, fmaf(e3, c1.w, fmaf(e4, d1.w, acc[7]))));
        } else {
            // slow path: segment boundary inside this group
            #pragma unroll
            for (int j = 0; j < 4; ++j) {
                int sj = __shfl_sync(0xffffffffu, sid, i + j);
                if (sj != cur) { flush(); cur = sj; c = calc_c(cur); }
                float q  = (j == 0) ? q1 : (j == 1) ? q2 : (j == 2) ? q3 : q4;
                float t  = c + q;
                float z  = t > 0.f ? t : 0.01f * t;
                float e  = __expf(z);
                if (j == 0) accum1(e, a0, a1);
                else if (j == 1) accum1(e, b0, b1);
                else if (j == 2) accum1(e, c0, c1);
                else accum1(e, d0, d1);
            }
        }
    }
    // tail (< 4 nodes)
    for (; i < cnt; ++i) {
        int sj = __shfl_sync(0xffffffffu, sid, i);
        if (sj != cur) { flush(); cur = sj; c = calc_c(cur); }
        const float4* fr = reinterpret_cast<const float4*>(nf + (size_t)(n0 + i) * F) + lane * 2;
        float4 f0 = ldcs4(fr), f1 = ldcs4(fr + 1);
        float d = f0.x * lw2[0];
        d = fmaf(f0.y, lw2[1], d); d = fmaf(f0.z, lw2[2], d); d = fmaf(f0.w, lw2[3], d);
        d = fmaf(f1.x, lw2[4], d); d = fmaf(f1.y, lw2[5], d);
        d = fmaf(f1.z, lw2[6], d); d = fmaf(f1.w, lw2[7], d);
        #pragma unroll
        for (int o = 16; o; o >>= 1) d += __shfl_xor_sync(0xffffffffu, d, o);
        float t = c + d;
        float z = t > 0.f ? t : 0.01f * t;
        accum1(__expf(z), f0, f1);
    }
    flush();
}

// ---------------- proj: x = elu((acc/S) @ pw.T + pb), zero when S==0 ----------------
// BM=BN=64, BK=16, TM=TN=4, 256 threads, double-buffered, FFMA2
__global__ void __launch_bounds__(256) proj_kernel(
    const float* __restrict__ pw, const float* __restrict__ pb)
{
    __shared__ float As[2][16][68];
    __shared__ float Ws[2][16][68];

    const int tid  = threadIdx.x;
    const int tx   = tid % 16;
    const int ty   = tid / 16;
    const int row0 = blockIdx.x * 64;
    const int col0 = blockIdx.y * 64;

    const int r_ld  = tid / 4;
    const int c4_ld = tid % 4;

    // normalization factor for this thread's load row (fixed across k)
    float Sv = g_s[row0 + r_ld];
    float rs = Sv > 0.f ? 1.f / Sv : 0.f;

    float4 aR, wR;
    auto ldg = [&](int k0) {
        aR = *reinterpret_cast<const float4*>(g_acc + (size_t)(row0 + r_ld) * F + k0 + c4_ld * 4);
        aR.x *= rs; aR.y *= rs; aR.z *= rs; aR.w *= rs;
        wR = *reinterpret_cast<const float4*>(pw + (size_t)(col0 + r_ld) * F + k0 + c4_ld * 4);
    };
    auto sts = [&](int buf) {
        As[buf][c4_ld * 4 + 0][r_ld] = aR.x;
        As[buf][c4_ld * 4 + 1][r_ld] = aR.y;
        As[buf][c4_ld * 4 + 2][r_ld] = aR.z;
        As[buf][c4_ld * 4 + 3][r_ld] = aR.w;
        Ws[buf][c4_ld * 4 + 0][r_ld] = wR.x;
        Ws[buf][c4_ld * 4 + 1][r_ld] = wR.y;
        Ws[buf][c4_ld * 4 + 2][r_ld] = wR.z;
        Ws[buf][c4_ld * 4 + 3][r_ld] = wR.w;
    };

    uint64_t acc2[4][2];
    #pragma unroll
    for (int i = 0; i < 4; ++i) { acc2[i][0] = 0ull; acc2[i][1] = 0ull; }

    ldg(0); sts(0); __syncthreads();
    for (int t = 0; t < 16; ++t) {
        if (t + 1 < 16) ldg((t + 1) * 16);
        const int buf = t & 1;
        #pragma unroll
        for (int kk = 0; kk < 16; ++kk) {
            float4 ra = *reinterpret_cast<const float4*>(&As[buf][kk][ty * 4]);
            float4 rw = *reinterpret_cast<const float4*>(&Ws[buf][kk][tx * 4]);
            uint64_t b01 = pack2(rw.x, rw.y);
            uint64_t b23 = pack2(rw.z, rw.w);
            uint64_t a0 = bcast2(ra.x), a1 = bcast2(ra.y);
            uint64_t a2 = bcast2(ra.z), a3 = bcast2(ra.w);
            ffma2(acc2[0][0], a0, b01); ffma2(acc2[0][1], a0, b23);
            ffma2(acc2[1][0], a1, b01); ffma2(acc2[1][1], a1, b23);
            ffma2(acc2[2][0], a2, b01); ffma2(acc2[2][1], a2, b23);
            ffma2(acc2[3][0], a3, b01); ffma2(acc2[3][1], a3, b23);
        }
        if (t + 1 < 16) { sts((t + 1) & 1); __syncthreads(); }
    }

    #pragma unroll
    for (int i = 0; i < 4; ++i) {
        int r = row0 + ty * 4 + i;
        bool nonempty = g_s[r] > 0.f;
        #pragma unroll
        for (int j = 0; j < 2; ++j) {
            int col = col0 + tx * 4 + j * 2;
            float2 v = unpack2(acc2[i][j]);
            v.x += pb[col];
            v.y += pb[col + 1];
            v.x = v.x > 0.f ? v.x : expm1f(v.x);
            v.y = v.y > 0.f ? v.y : expm1f(v.y);
            if (!nonempty) { v.x = 0.f; v.y = 0.f; }
            *reinterpret_cast<float2*>(g_x + (size_t)r * F + col) = v;
        }
    }
}

// ---------------- fused GRU GEMM: [x|h] @ [w_ih|w_hh]^T + full GRU epilogue ----
// Virtual K=512 (stages 0-7: x/w_ih, 8-15: h/w_hh). Shared accumulators for
// r/z gates, split accumulators for the n gate. Writes final output.
__global__ void __launch_bounds__(256) grugemm_kernel(
    const float* __restrict__ gf,
    const float* __restrict__ wih, const float* __restrict__ whh,
    const float* __restrict__ bih, const float* __restrict__ bhh,
    float* __restrict__ out)
{
    __shared__ float As[2][32][36];
    __shared__ float Ws[2][32][100];

    const int tid  = threadIdx.x;
    const int tx   = tid & 7;      // 0..7  -> 4 cols per gate
    const int ty   = tid >> 3;     // 0..31 -> 1 row
    const int row0 = blockIdx.x * 32;
    const int colg = blockIdx.y * 32;
    const int rA   = tid >> 3;     // load row 0..31
    const int c4   = tid & 7;      // load col group 0..7

    float4 aR, wR0, wR1, wR2;
    auto ldg = [&](int t) {
        int k0 = (t & 7) * 32;
        const float* Asrc = (t < 8) ? g_x : gf;
        const float* Wsrc = (t < 8) ? wih : whh;
        aR  = *reinterpret_cast<const float4*>(Asrc + (size_t)(row0 + rA) * F + k0 + c4 * 4);
        wR0 = *reinterpret_cast<const float4*>(Wsrc + (size_t)(0 * F + colg + rA) * F + k0 + c4 * 4);
        wR1 = *reinterpret_cast<const float4*>(Wsrc + (size_t)(1 * F + colg + rA) * F + k0 + c4 * 4);
        wR2 = *reinterpret_cast<const float4*>(Wsrc + (size_t)(2 * F + colg + rA) * F + k0 + c4 * 4);
    };
    auto sts = [&](int buf) {
        As[buf][c4 * 4 + 0][rA] = aR.x;
        As[buf][c4 * 4 + 1][rA] = aR.y;
        As[buf][c4 * 4 + 2][rA] = aR.z;
        As[buf][c4 * 4 + 3][rA] = aR.w;
        Ws[buf][c4 * 4 + 0][rA]      = wR0.x;
        Ws[buf][c4 * 4 + 1][rA]      = wR0.y;
        Ws[buf][c4 * 4 + 2][rA]      = wR0.z;
        Ws[buf][c4 * 4 + 3][rA]      = wR0.w;
        Ws[buf][c4 * 4 + 0][32 + rA] = wR1.x;
        Ws[buf][c4 * 4 + 1][32 + rA] = wR1.y;
        Ws[buf][c4 * 4 + 2][32 + rA] = wR1.z;
        Ws[buf][c4 * 4 + 3][32 + rA] = wR1.w;
        Ws[buf][c4 * 4 + 0][64 + rA] = wR2.x;
        Ws[buf][c4 * 4 + 1][64 + rA] = wR2.y;
        Ws[buf][c4 * 4 + 2][64 + rA] = wR2.z;
        Ws[buf][c4 * 4 + 3][64 + rA] = wR2.w;
    };

    uint64_t acc_r[2] = {0ull, 0ull};
    uint64_t acc_z[2] = {0ull, 0ull};
    uint64_t acc_in[2] = {0ull, 0ull};
    uint64_t acc_hn[2] = {0ull, 0ull};

    ldg(0); sts(0); __syncthreads();
    for (int t = 0; t < 16; ++t) {
        if (t + 1 < 16) ldg(t + 1);
        const int buf = t & 1;
        if (t < 8) {
            #pragma unroll
            for (int kk = 0; kk < 32; ++kk) {
                uint64_t aa = bcast2(As[buf][kk][ty]);
                float4 w0 = *reinterpret_cast<const float4*>(&Ws[buf][kk][tx * 4]);
                float4 w1 = *reinterpret_cast<const float4*>(&Ws[buf][kk][32 + tx * 4]);
                float4 w2 = *reinterpret_cast<const float4*>(&Ws[buf][kk][64 + tx * 4]);
                ffma2(acc_r[0], aa, pack2(w0.x, w0.y)); ffma2(acc_r[1], aa, pack2(w0.z, w0.w));
                ffma2(acc_z[0], aa, pack2(w1.x, w1.y)); ffma2(acc_z[1], aa, pack2(w1.z, w1.w));
                ffma2(acc_in[0], aa, pack2(w2.x, w2.y)); ffma2(acc_in[1], aa, pack2(w2.z, w2.w));
            }
        } else {
            #pragma unroll
            for (int kk = 0; kk < 32; ++kk) {
                uint64_t aa = bcast2(As[buf][kk][ty]);
                float4 w0 = *reinterpret_cast<const float4*>(&Ws[buf][kk][tx * 4]);
                float4 w1 = *reinterpret_cast<const float4*>(&Ws[buf][kk][32 + tx * 4]);
                float4 w2 = *reinterpret_cast<const float4*>(&Ws[buf][kk][64 + tx * 4]);
                ffma2(acc_r[0], aa, pack2(w0.x, w0.y)); ffma2(acc_r[1], aa, pack2(w0.z, w0.w));
                ffma2(acc_z[0], aa, pack2(w1.x, w1.y)); ffma2(acc_z[1], aa, pack2(w1.z, w1.w));
                ffma2(acc_hn[0], aa, pack2(w2.x, w2.y)); ffma2(acc_hn[1], aa, pack2(w2.z, w2.w));
            }
        }
        if (t + 1 < 16) { sts((t + 1) & 1); __syncthreads(); }
    }

    // ---- GRU epilogue ----
    const int r = row0 + ty;
    const int cc = colg + tx * 4;

    float2 r01 = unpack2(acc_r[0]),  r23 = unpack2(acc_r[1]);
    float2 z01 = unpack2(acc_z[0]),  z23 = unpack2(acc_z[1]);
    float2 i01 = unpack2(acc_in[0]), i23 = unpack2(acc_in[1]);
    float2 n01 = unpack2(acc_hn[0]), n23 = unpack2(acc_hn[1]);
    float gr[4] = {r01.x, r01.y, r23.x, r23.y};
    float gz[4] = {z01.x, z01.y, z23.x, z23.y};
    float gin[4] = {i01.x, i01.y, i23.x, i23.y};
    float ghn[4] = {n01.x, n01.y, n23.x, n23.y};

    float4 bir = *reinterpret_cast<const float4*>(bih + cc);
    float4 bhr = *reinterpret_cast<const float4*>(bhh + cc);
    float4 biz = *reinterpret_cast<const float4*>(bih + 256 + cc);
    float4 bhz = *reinterpret_cast<const float4*>(bhh + 256 + cc);
    float4 bin = *reinterpret_cast<const float4*>(bih + 512 + cc);
    float4 bhn = *reinterpret_cast<const float4*>(bhh + 512 + cc);
    float4 h   = *reinterpret_cast<const float4*>(gf + (size_t)r * F + cc);

    float br_[4] = {bir.x + bhr.x, bir.y + bhr.y, bir.z + bhr.z, bir.w + bhr.w};
    float bz_[4] = {biz.x + bhz.x, biz.y + bhz.y, biz.z + bhz.z, biz.w + bhz.w};
    float bi_[4] = {bin.x, bin.y, bin.z, bin.w};
    float bh_[4] = {bhn.x, bhn.y, bhn.z, bhn.w};
    float hv[4] = {h.x, h.y, h.z, h.w};

    float4 o;
    float* op = &o.x;
    #pragma unroll
    for (int k = 0; k < 4; ++k) {
        float rr = 0.5f * fast_tanh(0.5f * (gr[k] + br_[k])) + 0.5f;
        float zz = 0.5f * fast_tanh(0.5f * (gz[k] + bz_[k])) + 0.5f;
        float nn = fast_tanh(fmaf(rr, ghn[k] + bh_[k], gin[k] + bi_[k]));
        op[k] = fmaf(1.f - zz, nn, zz * hv[k]);
    }
    *reinterpret_cast<float4*>(out + (size_t)r * F + cc) = o;
}

// ---------------- launch ----------------
extern "C" void kernel_launch(void* const* d_in, const int* in_sizes, int n_in,
                              void* d_out, int out_size)
{
    int o = (n_in >= 12) ? 1 : 0;
    const float* nf  = (const float*)d_in[0];
    const float* gf  = (const float*)d_in[1];
    const int*   seg = (const int*)  d_in[2];
    const float* lw  = (const float*)d_in[3 + o];
    const float* lb  = (const float*)d_in[4 + o];
    const float* pw  = (const float*)d_in[5 + o];
    const float* pb  = (const float*)d_in[6 + o];
    const float* wih = (const float*)d_in[7 + o];
    const float* whh = (const float*)d_in[8 + o];
    const float* bih = (const float*)d_in[9 + o];
    const float* bhh = (const float*)d_in[10 + o];
    float* out = (float*)d_out;
    int n_nodes = in_sizes[0] / F;

    zero_kernel<<<256, 256>>>();
    pool_kernel<<<(n_nodes + 255) / 256, 256>>>(nf, gf, lw, lb, seg, n_nodes);
    proj_kernel<<<dim3(NG / 64, F / 64), 256>>>(pw, pb);
    grugemm_kernel<<<dim3(NG / 32, F / 32), 256>>>(gf, wih, whh, bih, bhh, out);
}

// round 7
// speedup vs baseline: 1.4773x; 1.4773x over previous
#include <cuda_runtime.h>
#include <math.h>
#include <stdint.h>

#define F   256
#define NG  1024

// GEMM tile config: BM=BN=64, BK=16, TM=TN=4, 256 threads
#define BM 64
#define BN 64
#define BK 16

#define GH_BX 16                  // 1024/64
#define GH_BY 12                  // 768/64
#define GH_BLOCKS (GH_BX * GH_BY) // 192

// ---------------- scratch ----------------
__device__ float g_wf[NG * F];
__device__ int   g_cnt[NG];
__device__ float g_x[NG * F];
__device__ float g_gi[NG * 3 * F];
__device__ float g_gh[NG * 3 * F];

// ---------------- f32x2 packed-math helpers ----------------
__device__ __forceinline__ uint64_t pack2(float x, float y) {
    uint64_t r; asm("mov.b64 %0, {%1, %2};" : "=l"(r) : "f"(x), "f"(y)); return r;
}
__device__ __forceinline__ uint64_t bcast2(float x) {
    uint64_t r; asm("mov.b64 %0, {%1, %1};" : "=l"(r) : "f"(x)); return r;
}
__device__ __forceinline__ void ffma2(uint64_t& d, uint64_t a, uint64_t b) {
    asm("fma.rn.f32x2 %0, %1, %2, %0;" : "+l"(d) : "l"(a), "l"(b));
}
__device__ __forceinline__ float2 unpack2(uint64_t v) {
    float2 f; asm("mov.b64 {%0, %1}, %2;" : "=f"(f.x), "=f"(f.y) : "l"(v)); return f;
}
__device__ __forceinline__ float fast_tanh(float x) {
    float r; asm("tanh.approx.f32 %0, %1;" : "=f"(r) : "f"(x)); return r;
}
__device__ __forceinline__ float4 ldcs4(const float4* p) {
    float4 v;
    asm("ld.global.cs.v4.f32 {%0,%1,%2,%3}, [%4];"
        : "=f"(v.x), "=f"(v.y), "=f"(v.z), "=f"(v.w) : "l"(p));
    return v;
}

// ---------------- shared memory layouts ----------------
struct SmemGemm {
    float As[2][BK][BM + 4];
    float Ws[2][BK][BN + 4];
};
struct SmemPool {
    float red[8];
    float c;
    float s[8];
    int   bnd[2];
    float acc[8][F];
};
union SmemU { SmemGemm g; SmemPool p; };

// ---------------- GEMM body: C[M,N] = A[M,K] @ W[N,K]^T + bias ----------------
template <int EPI>
__device__ __forceinline__ void gemm_body(
    SmemGemm& S,
    const float* __restrict__ A, const float* __restrict__ W,
    const float* __restrict__ bias, float* __restrict__ C,
    const int* __restrict__ cnt, int N, int K, int bx, int by)
{
    const int tid  = threadIdx.x;
    const int tx   = tid % (BN / 4);
    const int ty   = tid / (BN / 4);
    const int row0 = bx * BM;
    const int col0 = by * BN;

    float4 aR, wR;
    const int r_ld  = tid / (BK / 4);
    const int c4_ld = tid % (BK / 4);

    auto ldg = [&](int k0) {
        aR = *reinterpret_cast<const float4*>(A + (size_t)(row0 + r_ld) * K + k0 + c4_ld * 4);
        wR = *reinterpret_cast<const float4*>(W + (size_t)(col0 + r_ld) * K + k0 + c4_ld * 4);
    };
    auto sts = [&](int buf) {
        S.As[buf][c4_ld * 4 + 0][r_ld] = aR.x;
        S.As[buf][c4_ld * 4 + 1][r_ld] = aR.y;
        S.As[buf][c4_ld * 4 + 2][r_ld] = aR.z;
        S.As[buf][c4_ld * 4 + 3][r_ld] = aR.w;
        S.Ws[buf][c4_ld * 4 + 0][r_ld] = wR.x;
        S.Ws[buf][c4_ld * 4 + 1][r_ld] = wR.y;
        S.Ws[buf][c4_ld * 4 + 2][r_ld] = wR.z;
        S.Ws[buf][c4_ld * 4 + 3][r_ld] = wR.w;
    };

    uint64_t acc2[4][2];
    #pragma unroll
    for (int i = 0; i < 4; ++i) { acc2[i][0] = 0ull; acc2[i][1] = 0ull; }

    const int T = K / BK;
    ldg(0);
    sts(0);
    __syncthreads();

    for (int t = 0; t < T; ++t) {
        if (t + 1 < T) ldg((t + 1) * BK);
        const int buf = t & 1;
        #pragma unroll
        for (int kk = 0; kk < BK; ++kk) {
            float4 ra = *reinterpret_cast<const float4*>(&S.As[buf][kk][ty * 4]);
            float4 rw = *reinterpret_cast<const float4*>(&S.Ws[buf][kk][tx * 4]);
            uint64_t b01 = pack2(rw.x, rw.y);
            uint64_t b23 = pack2(rw.z, rw.w);
            uint64_t a0 = bcast2(ra.x), a1 = bcast2(ra.y);
            uint64_t a2 = bcast2(ra.z), a3 = bcast2(ra.w);
            ffma2(acc2[0][0], a0, b01); ffma2(acc2[0][1], a0, b23);
            ffma2(acc2[1][0], a1, b01); ffma2(acc2[1][1], a1, b23);
            ffma2(acc2[2][0], a2, b01); ffma2(acc2[2][1], a2, b23);
            ffma2(acc2[3][0], a3, b01); ffma2(acc2[3][1], a3, b23);
        }
        if (t + 1 < T) {
            sts((t + 1) & 1);
            __syncthreads();
        }
    }

    #pragma unroll
    for (int i = 0; i < 4; ++i) {
        int r = row0 + ty * 4 + i;
        int cz = (EPI == 1) ? cnt[r] : 1;
        #pragma unroll
        for (int j = 0; j < 2; ++j) {
            int col = col0 + tx * 4 + j * 2;
            float2 v = unpack2(acc2[i][j]);
            v.x += bias[col];
            v.y += bias[col + 1];
            if (EPI == 1) {
                v.x = v.x > 0.f ? v.x : expm1f(v.x);
                v.y = v.y > 0.f ? v.y : expm1f(v.y);
                if (cz == 0) { v.x = 0.f; v.y = 0.f; }
            }
            *reinterpret_cast<float2*>(C + (size_t)r * N + col) = v;
        }
    }
}

// ---------------- binary search (segment_ids sorted) ----------------
__device__ __forceinline__ int lbound(const int* __restrict__ seg, int n, int key) {
    int lo = 0, hi = n;
    while (lo < hi) {
        int mid = (lo + hi) >> 1;
        if (__ldg(seg + mid) < key) lo = mid + 1; else hi = mid;
    }
    return lo;
}

// ---------------- fused: GH GEMM blocks + pool blocks ----------------
// Pool: unnormalized exp accumulation (scale cancels in val/S; z bounded for
// unit-normal inputs). Unroll-4 with front-batched loads. COALESCED lane
// mapping: lane owns dims [4*lane, 4*lane+4) and [128+4*lane, 128+4*lane+4),
// so every LDG.128 is a single contiguous 512B warp transaction (4 lines).
__global__ void __launch_bounds__(256) fused_pool_gh_kernel(
    const float* __restrict__ nf, const float* __restrict__ gf,
    const float* __restrict__ lw, const float* __restrict__ lb,
    const float* __restrict__ whh, const float* __restrict__ bhh,
    const int* __restrict__ seg, int n_nodes)
{
    __shared__ SmemU sm;

    if (blockIdx.x < GH_BLOCKS) {
        int bx = blockIdx.x % GH_BX;
        int by = blockIdx.x / GH_BX;
        gemm_body<0>(sm.g, gf, whh, bhh, g_gh, nullptr, 3 * F, F, bx, by);
        return;
    }

    const int g    = blockIdx.x - GH_BLOCKS;
    const int tid  = threadIdx.x;
    const int warp = tid >> 5;
    const int lane = tid & 31;

    // c_g = relu(g_feats[g]) . lw[0:256] + b
    {
        float v = fmaxf(gf[g * F + tid], 0.f) * lw[tid];
        #pragma unroll
        for (int o = 16; o; o >>= 1) v += __shfl_xor_sync(0xffffffffu, v, o);
        if (lane == 0) sm.p.red[warp] = v;
    }
    if (tid == 0)  sm.p.bnd[0] = lbound(seg, n_nodes, g);
    if (tid == 32) sm.p.bnd[1] = lbound(seg, n_nodes, g + 1);
    __syncthreads();
    if (tid == 0) {
        float c = lb[0];
        #pragma unroll
        for (int w = 0; w < 8; ++w) c += sm.p.red[w];
        sm.p.c = c;
    }
    __syncthreads();
    const float c     = sm.p.c;
    const int   start = sm.p.bnd[0];
    const int   end   = sm.p.bnd[1];

    // per-lane chunks of logit_w node half (coalesced mapping):
    // lwA = dims [4*lane,4*lane+4), lwB = dims [128+4*lane, ...)
    float lwA[4], lwB[4];
    {
        float4 a = __ldg(reinterpret_cast<const float4*>(lw + F) + lane);
        float4 b = __ldg(reinterpret_cast<const float4*>(lw + F + 128) + lane);
        lwA[0]=a.x; lwA[1]=a.y; lwA[2]=a.z; lwA[3]=a.w;
        lwB[0]=b.x; lwB[1]=b.y; lwB[2]=b.z; lwB[3]=b.w;
    }

    float s = 0.f;
    float acc[8] = {0.f, 0.f, 0.f, 0.f, 0.f, 0.f, 0.f, 0.f};

    int n = start + warp;
    // ---- main loop: 4 nodes per iteration, 8 front-batched contiguous LDG.128 ----
    for (; n + 24 < end; n += 32) {
        // row stride in float4: F/4 = 64; node step is 8 rows = 512 float4
        const float4* p = reinterpret_cast<const float4*>(nf + (size_t)n * F) + lane;
        float4 a0 = ldcs4(p),        a1 = ldcs4(p + 32);
        float4 b0 = ldcs4(p + 512),  b1 = ldcs4(p + 544);
        float4 c0 = ldcs4(p + 1024), c1 = ldcs4(p + 1056);
        float4 d0 = ldcs4(p + 1536), d1 = ldcs4(p + 1568);

        float q1 = a0.x * lwA[0], q2 = b0.x * lwA[0];
        float q3 = c0.x * lwA[0], q4 = d0.x * lwA[0];
        q1 = fmaf(a0.y, lwA[1], q1); q2 = fmaf(b0.y, lwA[1], q2);
        q3 = fmaf(c0.y, lwA[1], q3); q4 = fmaf(d0.y, lwA[1], q4);
        q1 = fmaf(a0.z, lwA[2], q1); q2 = fmaf(b0.z, lwA[2], q2);
        q3 = fmaf(c0.z, lwA[2], q3); q4 = fmaf(d0.z, lwA[2], q4);
        q1 = fmaf(a0.w, lwA[3], q1); q2 = fmaf(b0.w, lwA[3], q2);
        q3 = fmaf(c0.w, lwA[3], q3); q4 = fmaf(d0.w, lwA[3], q4);
        q1 = fmaf(a1.x, lwB[0], q1); q2 = fmaf(b1.x, lwB[0], q2);
        q3 = fmaf(c1.x, lwB[0], q3); q4 = fmaf(d1.x, lwB[0], q4);
        q1 = fmaf(a1.y, lwB[1], q1); q2 = fmaf(b1.y, lwB[1], q2);
        q3 = fmaf(c1.y, lwB[1], q3); q4 = fmaf(d1.y, lwB[1], q4);
        q1 = fmaf(a1.z, lwB[2], q1); q2 = fmaf(b1.z, lwB[2], q2);
        q3 = fmaf(c1.z, lwB[2], q3); q4 = fmaf(d1.z, lwB[2], q4);
        q1 = fmaf(a1.w, lwB[3], q1); q2 = fmaf(b1.w, lwB[3], q2);
        q3 = fmaf(c1.w, lwB[3], q3); q4 = fmaf(d1.w, lwB[3], q4);
        #pragma unroll
        for (int o = 16; o; o >>= 1) {
            q1 += __shfl_xor_sync(0xffffffffu, q1, o);
            q2 += __shfl_xor_sync(0xffffffffu, q2, o);
            q3 += __shfl_xor_sync(0xffffffffu, q3, o);
            q4 += __shfl_xor_sync(0xffffffffu, q4, o);
        }
        float t1 = c + q1, t2 = c + q2, t3 = c + q3, t4 = c + q4;
        float z1 = t1 > 0.f ? t1 : 0.01f * t1;
        float z2 = t2 > 0.f ? t2 : 0.01f * t2;
        float z3 = t3 > 0.f ? t3 : 0.01f * t3;
        float z4 = t4 > 0.f ? t4 : 0.01f * t4;
        float e1 = __expf(z1), e2 = __expf(z2);
        float e3 = __expf(z3), e4 = __expf(z4);
        s += (e1 + e2) + (e3 + e4);
        acc[0] = fmaf(e1, a0.x, fmaf(e2, b0.x, fmaf(e3, c0.x, fmaf(e4, d0.x, acc[0]))));
        acc[1] = fmaf(e1, a0.y, fmaf(e2, b0.y, fmaf(e3, c0.y, fmaf(e4, d0.y, acc[1]))));
        acc[2] = fmaf(e1, a0.z, fmaf(e2, b0.z, fmaf(e3, c0.z, fmaf(e4, d0.z, acc[2]))));
        acc[3] = fmaf(e1, a0.w, fmaf(e2, b0.w, fmaf(e3, c0.w, fmaf(e4, d0.w, acc[3]))));
        acc[4] = fmaf(e1, a1.x, fmaf(e2, b1.x, fmaf(e3, c1.x, fmaf(e4, d1.x, acc[4]))));
        acc[5] = fmaf(e1, a1.y, fmaf(e2, b1.y, fmaf(e3, c1.y, fmaf(e4, d1.y, acc[5]))));
        acc[6] = fmaf(e1, a1.z, fmaf(e2, b1.z, fmaf(e3, c1.z, fmaf(e4, d1.z, acc[6]))));
        acc[7] = fmaf(e1, a1.w, fmaf(e2, b1.w, fmaf(e3, c1.w, fmaf(e4, d1.w, acc[7]))));
    }
    // ---- tail: up to 3 nodes per warp ----
    for (; n < end; n += 8) {
        const float4* p = reinterpret_cast<const float4*>(nf + (size_t)n * F) + lane;
        float4 f0 = ldcs4(p), f1 = ldcs4(p + 32);
        float d = f0.x * lwA[0];
        d = fmaf(f0.y, lwA[1], d); d = fmaf(f0.z, lwA[2], d); d = fmaf(f0.w, lwA[3], d);
        d = fmaf(f1.x, lwB[0], d); d = fmaf(f1.y, lwB[1], d);
        d = fmaf(f1.z, lwB[2], d); d = fmaf(f1.w, lwB[3], d);
        #pragma unroll
        for (int o = 16; o; o >>= 1) d += __shfl_xor_sync(0xffffffffu, d, o);
        float t  = c + d;
        float z  = t > 0.f ? t : 0.01f * t;
        float e  = __expf(z);
        s += e;
        acc[0] = fmaf(e, f0.x, acc[0]);
        acc[1] = fmaf(e, f0.y, acc[1]);
        acc[2] = fmaf(e, f0.z, acc[2]);
        acc[3] = fmaf(e, f0.w, acc[3]);
        acc[4] = fmaf(e, f1.x, acc[4]);
        acc[5] = fmaf(e, f1.y, acc[5]);
        acc[6] = fmaf(e, f1.z, acc[6]);
        acc[7] = fmaf(e, f1.w, acc[7]);
    }

    if (lane == 0) sm.p.s[warp] = s;
    // coalesced dim mapping: acc[0..3] -> dims 4*lane+j ; acc[4..7] -> 128+4*lane+j
    #pragma unroll
    for (int j = 0; j < 4; ++j) {
        sm.p.acc[warp][lane * 4 + j]       = acc[j];
        sm.p.acc[warp][128 + lane * 4 + j] = acc[4 + j];
    }
    __syncthreads();

    float S = 0.f, val = 0.f;
    #pragma unroll
    for (int w = 0; w < 8; ++w) {
        S   += sm.p.s[w];
        val += sm.p.acc[w][tid];
    }
    g_wf[g * F + tid] = (S > 0.f) ? val / S : 0.f;
    if (tid == 0) g_cnt[g] = end - start;
}

// proj: x = elu(wf @ proj_w.T + proj_b), zeroed for empty graphs
__global__ void __launch_bounds__(256) proj_kernel(
    const float* __restrict__ pw, const float* __restrict__ pb)
{
    __shared__ SmemGemm sg;
    gemm_body<1>(sg, g_wf, pw, pb, g_x, g_cnt, F, F, blockIdx.x, blockIdx.y);
}

// GI = x @ w_ih.T + b_ih
__global__ void __launch_bounds__(256) gi_kernel(
    const float* __restrict__ wih, const float* __restrict__ bih)
{
    __shared__ SmemGemm sg;
    gemm_body<0>(sg, g_x, wih, bih, g_gi, nullptr, 3 * F, F, blockIdx.x, blockIdx.y);
}

// ---------------- GRU elementwise (float2, 512 blocks) ----------------
__global__ void __launch_bounds__(256) gru_kernel(
    const float* __restrict__ gf, float* __restrict__ out)
{
    int idx2 = blockIdx.x * blockDim.x + threadIdx.x;
    if (idx2 >= NG * F / 2) return;
    int g  = idx2 / (F / 2);
    int d2 = (idx2 % (F / 2)) * 2;
    const float* gi = g_gi + (size_t)g * 3 * F;
    const float* gh = g_gh + (size_t)g * 3 * F;

    float2 ir  = *reinterpret_cast<const float2*>(gi + d2);
    float2 iz  = *reinterpret_cast<const float2*>(gi + F + d2);
    float2 inn = *reinterpret_cast<const float2*>(gi + 2 * F + d2);
    float2 hr  = *reinterpret_cast<const float2*>(gh + d2);
    float2 hz  = *reinterpret_cast<const float2*>(gh + F + d2);
    float2 hn  = *reinterpret_cast<const float2*>(gh + 2 * F + d2);
    float2 h   = *reinterpret_cast<const float2*>(gf + (size_t)g * F + d2);

    float2 o;
    {
        float r = 0.5f * fast_tanh(0.5f * (ir.x + hr.x)) + 0.5f;
        float z = 0.5f * fast_tanh(0.5f * (iz.x + hz.x)) + 0.5f;
        float nn = fast_tanh(fmaf(r, hn.x, inn.x));
        o.x = fmaf(1.f - z, nn, z * h.x);
    }
    {
        float r = 0.5f * fast_tanh(0.5f * (ir.y + hr.y)) + 0.5f;
        float z = 0.5f * fast_tanh(0.5f * (iz.y + hz.y)) + 0.5f;
        float nn = fast_tanh(fmaf(r, hn.y, inn.y));
        o.y = fmaf(1.f - z, nn, z * h.y);
    }
    *reinterpret_cast<float2*>(out + (size_t)g * F + d2) = o;
}

// ---------------- launch ----------------
extern "C" void kernel_launch(void* const* d_in, const int* in_sizes, int n_in,
                              void* d_out, int out_size)
{
    int o = (n_in >= 12) ? 1 : 0;
    const float* nf  = (const float*)d_in[0];
    const float* gf  = (const float*)d_in[1];
    const int*   seg = (const int*)  d_in[2];
    const float* lw  = (const float*)d_in[3 + o];
    const float* lb  = (const float*)d_in[4 + o];
    const float* pw  = (const float*)d_in[5 + o];
    const float* pb  = (const float*)d_in[6 + o];
    const float* wih = (const float*)d_in[7 + o];
    const float* whh = (const float*)d_in[8 + o];
    const float* bih = (const float*)d_in[9 + o];
    const float* bhh = (const float*)d_in[10 + o];
    float* out = (float*)d_out;
    int n_nodes = in_sizes[0] / F;

    fused_pool_gh_kernel<<<GH_BLOCKS + NG, 256>>>(nf, gf, lw, lb, whh, bhh, seg, n_nodes);
    proj_kernel<<<dim3(NG / BM, F / BN), 256>>>(pw, pb);
    gi_kernel<<<dim3(NG / BM, (3 * F) / BN), 256>>>(wih, bih);
    gru_kernel<<<(NG * F / 2 + 255) / 256, 256>>>(gf, out);
}